// round 13
// baseline (speedup 1.0000x reference)
#include <cuda_runtime.h>
#include <cuda_bf16.h>

// SpatialConv SCNN, GB300 sm_103a.
// R13: H pass uses cluster-4 HW barriers (+cp.async.cg, epilogue RMW prefetch);
// W pass splits cluster arrive/wait to overlap reduction with peer arrival.
// Core FFMA2 compute unchanged from R11/R12.

#define BB 64
#define CC 128
#define HH 36
#define WW 100
#define KK 9

typedef unsigned long long u64;

__device__ float g_T[(size_t)BB * CC * WW * HH];
__device__ float g_Wt[4][CC * CC * KK];            // [ci*9+k][co]

__device__ __forceinline__ void ffma2(u64& d, u64 a, u64 b) {
    asm("fma.rn.f32x2 %0, %1, %2, %0;" : "+l"(d) : "l"(a), "l"(b));
}
__device__ __forceinline__ u64 pack2(float a, float b) {
    u64 r; asm("mov.b64 %0, {%1, %2};" : "=l"(r) : "f"(a), "f"(b)); return r;
}
__device__ __forceinline__ void unpack2(u64 v, float& a, float& b) {
    asm("mov.b64 {%0, %1}, %2;" : "=f"(a), "=f"(b) : "l"(v));
}
__device__ __forceinline__ unsigned smem_u32(const void* p) {
    unsigned a;
    asm("{ .reg .u64 t; cvta.to.shared.u64 t, %1; cvt.u32.u64 %0, t; }"
        : "=r"(a) : "l"(p));
    return a;
}
__device__ __forceinline__ unsigned mapa_u32(unsigned laddr, unsigned rank) {
    unsigned r;
    asm("mapa.shared::cluster.u32 %0, %1, %2;" : "=r"(r) : "r"(laddr), "r"(rank));
    return r;
}
__device__ __forceinline__ void st_cluster64(unsigned addr, u64 v) {
    asm volatile("st.shared::cluster.u64 [%0], %1;" :: "r"(addr), "l"(v) : "memory");
}
__device__ __forceinline__ void cluster_arrive() {
    asm volatile("barrier.cluster.arrive.aligned;" ::: "memory");
}
__device__ __forceinline__ void cluster_wait() {
    asm volatile("barrier.cluster.wait.aligned;" ::: "memory");
}
__device__ __forceinline__ void cluster_sync() { cluster_arrive(); cluster_wait(); }
__device__ __forceinline__ void cp_async16(unsigned dst, const void* src, int srcsize) {
    asm volatile("cp.async.cg.shared.global [%0], [%1], 16, %2;"
                 :: "r"(dst), "l"(src), "r"(srcsize) : "memory");
}
#define CP_COMMIT() asm volatile("cp.async.commit_group;" ::: "memory")
#define CP_WAIT0()  asm volatile("cp.async.wait_group 0;" ::: "memory")

__global__ void dummy_kernel() {}

// ========== H pass: cp.async.cg staging, cluster-4 barrier ================
// buf [B][C][S=36][L=100]. Cluster = 4 co-quarter CTAs of one batch-pair.
template <int L, int S, int CP, int LG, int NL, int CIS>
__global__ __launch_bounds__(2 * CP * LG * CIS, 1) __cluster_dims__(4, 1, 1)
void pass_kernel(float* __restrict__ buf,
                 const float* __restrict__ wt, const float* __restrict__ bias,
                 int s_begin, int nsteps, int dir)
{
    constexpr int CO_TILE = 4 * CP;
    constexpr int WIN  = LG * NL + 8;
    constexpr int WINQ = WIN / 4;
    constexpr int NT   = 2 * CP * LG * CIS;
    constexpr int CIC  = 32;
    constexpr int NCHUNK = CC / CIC;
    constexpr int RPC  = CIC / CIS;
    static_assert(LG * NL == L, "");
    static_assert((NL & 1) == 0 && (L & 3) == 0 && (WIN & 3) == 0, "");

    extern __shared__ __align__(16) char smem_raw[];
    float* w_all = (float*)smem_raw;
    float* in_d  = w_all + CC * KK * CO_TILE;
    float* red   = in_d;

    const int tid  = threadIdx.x;
    const int lg   = tid % LG;
    const int cp   = (tid / LG) % CP;
    const int bsel = (tid / (LG * CP)) % 2;
    const int cis  = tid / (LG * CP * 2);
    const int b0   = blockIdx.y * 2;
    const int co_base = blockIdx.x * CO_TILE;
    const unsigned in_u32 = smem_u32(in_d);

    for (int idx = tid; idx < CC * KK * CO_TILE; idx += NT)
        w_all[idx] = wt[(size_t)(idx / CO_TILE) * CC + co_base + (idx % CO_TILE)];

    u64 bias01, bias23;
    {
        float v0 = bias[co_base + 4 * cp + 0];
        float v1 = bias[co_base + 4 * cp + 1];
        float v2 = bias[co_base + 4 * cp + 2];
        float v3 = bias[co_base + 4 * cp + 3];
        bias01 = (cis == 0) ? pack2(v0, v1) : 0ull;
        bias23 = (cis == 0) ? pack2(v2, v3) : 0ull;
    }
    __syncthreads();

    for (int it = 0; it < nsteps; it++) {
        const int s_dst = s_begin + it * dir;
        const int s_src = s_dst - dir;

        auto issue_chunk = [&](int cc, int pb) {
            for (int idx = tid; idx < 2 * CIC * WINQ; idx += NT) {
                int bs = idx / (CIC * WINQ);
                int rem = idx % (CIC * WINQ);
                int r = rem / WINQ, q = rem % WINQ;
                int ci = (r / RPC) * (CC / CIS) + cc * RPC + (r % RPC);
                int gl4 = q * 4 - 4;
                int ssz = (gl4 < 0 || gl4 + 3 >= L) ? 0 : 16;
                int gls = gl4 < 0 ? 0 : gl4;
                const float* src =
                    &buf[((size_t)((b0 + bs) * CC + ci) * S + s_src) * L + gls];
                unsigned dst = in_u32 +
                    (unsigned)((((pb * 2 + bs) * CIC + r) * WIN + q * 4) * 4);
                cp_async16(dst, src, ssz);
            }
            CP_COMMIT();
        };

        issue_chunk(0, 0);

        // Prefetch epilogue residual base (cis0 only) — overlaps chunk0 wait.
        float og[4 * NL / 2 * 2];  // 4 co x NL floats
        if (cis == 0) {
#pragma unroll
            for (int q = 0; q < 4; q++) {
                const float2* src = (const float2*)
                    &buf[((size_t)((b0 + bsel) * CC + co_base + 4 * cp + q) * S + s_dst)
                         * L + lg * NL];
#pragma unroll
                for (int t = 0; t < NL / 2; t++)
                    ((float2*)og)[q * (NL / 2) + t] = src[t];
            }
        }

        CP_WAIT0();
        __syncthreads();

        u64 acc0[NL], acc1[NL];
#pragma unroll
        for (int j = 0; j < NL; j++) { acc0[j] = bias01; acc1[j] = bias23; }

        for (int c = 0; c < NCHUNK; c++) {
            const int p = c & 1;
            if (c < NCHUNK - 1) issue_chunk(c + 1, p ^ 1);

#pragma unroll 2
            for (int rI = 0; rI < RPC; rI++) {
                const int r = cis * RPC + rI;
                const int ci = cis * (CC / CIS) + c * RPC + rI;
                const float* srow = &in_d[((p * 2 + bsel) * CIC + r) * WIN + lg * NL];
                u64 xx[NL + 8];
#pragma unroll
                for (int t = 0; t < (NL + 8) / 2; t++) {
                    float2 f = ((const float2*)srow)[t];
                    xx[2 * t + 0] = pack2(f.x, f.x);
                    xx[2 * t + 1] = pack2(f.y, f.y);
                }
                const float* wr = &w_all[(size_t)(ci * KK) * CO_TILE + 4 * cp];
#pragma unroll
                for (int k = 0; k < KK; k++) {
                    ulonglong2 wv = *(const ulonglong2*)(wr + k * CO_TILE);
#pragma unroll
                    for (int j = 0; j < NL; j++) {
                        ffma2(acc0[j], wv.x, xx[j + k]);
                        ffma2(acc1[j], wv.y, xx[j + k]);
                    }
                }
            }
            if (c < NCHUNK - 1) {
                CP_WAIT0();
                __syncthreads();
            }
        }
        __syncthreads();

        if (CIS > 1) {
            if (cis > 0) {
                float* pr = &red[((size_t)(cis - 1) * 2 + bsel) * CO_TILE * L];
#pragma unroll
                for (int j = 0; j < NL; j++) {
                    int l = lg * NL + j;
                    float a, bb, cv, d;
                    unpack2(acc0[j], a, bb); unpack2(acc1[j], cv, d);
                    pr[(4 * cp + 0) * L + l] = a;
                    pr[(4 * cp + 1) * L + l] = bb;
                    pr[(4 * cp + 2) * L + l] = cv;
                    pr[(4 * cp + 3) * L + l] = d;
                }
            }
            __syncthreads();
        }

        if (cis == 0) {
            float fin[4];
#pragma unroll
            for (int j = 0; j < NL; j++) {
                int l = lg * NL + j;
                float a, bb, cv, d;
                unpack2(acc0[j], a, bb); unpack2(acc1[j], cv, d);
#pragma unroll
                for (int c2 = 1; c2 < CIS; c2++) {
                    const float* pr = &red[((size_t)(c2 - 1) * 2 + bsel) * CO_TILE * L];
                    a  += pr[(4 * cp + 0) * L + l];
                    bb += pr[(4 * cp + 1) * L + l];
                    cv += pr[(4 * cp + 2) * L + l];
                    d  += pr[(4 * cp + 3) * L + l];
                }
                fin[0] = og[0 * NL + j] + fmaxf(a, 0.f);
                fin[1] = og[1 * NL + j] + fmaxf(bb, 0.f);
                fin[2] = og[2 * NL + j] + fmaxf(cv, 0.f);
                fin[3] = og[3 * NL + j] + fmaxf(d, 0.f);
                size_t base = ((size_t)((b0 + bsel) * CC + co_base + 4 * cp) * S + s_dst) * L + l;
                buf[base + 0 * S * L] = fin[0];
                buf[base + 1 * S * L] = fin[1];
                buf[base + 2 * S * L] = fin[2];
                buf[base + 3 * S * L] = fin[3];
            }
        }

        cluster_sync();   // HW barrier; IVALL keeps peer data fresh
    }
}

// ============ W pass: cluster-4, DSMEM push, split arrive/wait =============
#define W_L   36
#define W_S   100
#define W_ROW 44
#define W_NT  384

__global__ __launch_bounds__(W_NT, 1) __cluster_dims__(4, 1, 1)
void wpass_kernel(float* __restrict__ buf,
                  const float* __restrict__ wt, const float* __restrict__ bias,
                  int s_begin, int nsteps, int dir)
{
    extern __shared__ __align__(16) char smem_raw[];
    float* w_all  = (float*)smem_raw;                 // 128*9*32
    float* state  = w_all + CC * KK * 32;             // [2][128][44]
    float* red    = state + 2 * CC * W_ROW;           // 3 * 2304
    float* newcol = red + 3 * 2304;                   // [2][32][36]

    const int tid  = threadIdx.x;
    const int lg   = tid % 3;
    const int cp   = (tid / 3) % 16;
    const int bsel = (tid / 48) % 2;
    const int cis  = tid / 96;
    const int b0   = blockIdx.y * 2;
    const int co_base = blockIdx.x * 32;
    const unsigned state_u32 = smem_u32(state);

    for (int idx = tid; idx < CC * KK * 32; idx += W_NT)
        w_all[idx] = wt[(size_t)(idx / 32) * CC + co_base + (idx % 32)];

    for (int idx = tid; idx < 2 * CC * W_ROW; idx += W_NT) state[idx] = 0.f;
    __syncthreads();
    {
        const int s0 = s_begin - dir;
        for (int idx = tid; idx < 2 * CC * 9; idx += W_NT) {
            int bs = idx / (CC * 9);
            int r  = idx % (CC * 9);
            int ci = r / 9, q = r % 9;
            const float4* src = (const float4*)
                &buf[(((size_t)(b0 + bs) * CC + ci) * W_S + s0) * W_L];
            ((float4*)&state[(bs * CC + ci) * W_ROW + 4])[q] = src[q];
        }
    }

    const u64 biasp = (cis == 0)
        ? pack2(bias[co_base + 2 * cp], bias[co_base + 2 * cp + 1]) : 0ull;
    __syncthreads();

    for (int it = 0; it < nsteps; it++) {
        const int s_dst = s_begin + it * dir;

        // Residual target (doesn't touch state) — overlaps push-wait below.
        float4 og[6];
        if (cis == 0) {
#pragma unroll
            for (int q = 0; q < 2; q++) {
                const float4* src = (const float4*)
                    &buf[(((size_t)(b0 + bsel) * CC + co_base + 2 * cp + q) * W_S + s_dst)
                         * W_L + lg * 12];
#pragma unroll
                for (int t = 0; t < 3; t++) og[q * 3 + t] = src[t];
            }
        }

        if (it > 0) cluster_wait();   // pushes of step it-1 visible

        u64 acc[12];
#pragma unroll
        for (int j = 0; j < 12; j++) acc[j] = biasp;

#pragma unroll 2
        for (int i = 0; i < 32; i++) {
            const int ci = cis * 32 + i;
            const float* srow = &state[(bsel * CC + ci) * W_ROW + lg * 12];
            u64 xx[20];
#pragma unroll
            for (int t = 0; t < 5; t++) {
                float4 f = ((const float4*)srow)[t];
                xx[4 * t + 0] = pack2(f.x, f.x);
                xx[4 * t + 1] = pack2(f.y, f.y);
                xx[4 * t + 2] = pack2(f.z, f.z);
                xx[4 * t + 3] = pack2(f.w, f.w);
            }
            const float* wr = &w_all[(size_t)(ci * KK) * 32 + 2 * cp];
#pragma unroll
            for (int k = 0; k < KK; k++) {
                u64 wv = *(const u64*)(wr + k * 32);
#pragma unroll
                for (int j = 0; j < 12; j++) ffma2(acc[j], wv, xx[j + k]);
            }
        }
        __syncthreads();      // this CTA's state reads done
        cluster_arrive();     // signal reads-done; peers' reduction overlaps

        if (cis > 0) {
            float* pr = &red[(size_t)(cis - 1) * 2304];
#pragma unroll
            for (int j = 0; j < 12; j++) {
                int l = lg * 12 + j;
                float a, b2; unpack2(acc[j], a, b2);
                pr[(bsel * 32 + 2 * cp + 0) * W_L + l] = a;
                pr[(bsel * 32 + 2 * cp + 1) * W_L + l] = b2;
            }
        }
        __syncthreads();

        if (cis == 0) {
            float fin[24];
#pragma unroll
            for (int j = 0; j < 12; j++) {
                int l = lg * 12 + j;
                int f0 = (bsel * 32 + 2 * cp + 0) * W_L + l;
                int f1 = (bsel * 32 + 2 * cp + 1) * W_L + l;
                float a, b2; unpack2(acc[j], a, b2);
                a  += red[f0] + red[2304 + f0] + red[4608 + f0];
                b2 += red[f1] + red[2304 + f1] + red[4608 + f1];
                fin[j]      = ((const float*)og)[j]      + fmaxf(a, 0.f);
                fin[12 + j] = ((const float*)og)[12 + j] + fmaxf(b2, 0.f);
            }
#pragma unroll
            for (int q = 0; q < 2; q++) {
                float4* dst = (float4*)
                    &buf[(((size_t)(b0 + bsel) * CC + co_base + 2 * cp + q) * W_S + s_dst)
                         * W_L + lg * 12];
                float4* nst = (float4*)
                    &newcol[(bsel * 32 + 2 * cp + q) * W_L + lg * 12];
#pragma unroll
                for (int t = 0; t < 3; t++) {
                    float4 v = ((const float4*)fin)[q * 3 + t];
                    dst[t] = v;
                    nst[t] = v;
                }
            }
        }
        __syncthreads();      // newcol staged

        cluster_wait();       // all CTAs' reads done -> safe to push

        for (int idx = tid; idx < 2 * 32 * (W_L / 2); idx += W_NT) {
            int bs = idx / (32 * 18);
            int r  = idx % (32 * 18);
            int co = r / 18, q = r % 18;
            u64 v = ((const u64*)&newcol[(bs * 32 + co) * W_L])[q];
            unsigned loff = state_u32 +
                (unsigned)(((bs * CC + co_base + co) * W_ROW + 4) * 4 + q * 8);
#pragma unroll
            for (unsigned rk = 0; rk < 4; rk++)
                st_cluster64(mapa_u32(loff, rk), v);
        }

        cluster_arrive();     // pushes done; matched by next iter's wait
    }
    cluster_wait();           // drain before exit (peers may target our smem)
}

// [co][ci][k] -> [ci*9+k][co] for all 4 sets
__global__ void prep_w4(const float* __restrict__ w0, const float* __restrict__ w1,
                        const float* __restrict__ w2, const float* __restrict__ w3,
                        float* __restrict__ wt)
{
    int idx = blockIdx.x * 256 + threadIdx.x;
    if (idx < CC * CC * KK) {
        int co = idx / (CC * KK);
        int rem = idx % (CC * KK);
        int ci = rem / KK, k = rem % KK;
        size_t o = ((size_t)ci * KK + k) * CC + co;
        const size_t SZ = (size_t)CC * CC * KK;
        wt[o] = w0[idx];
        wt[SZ + o] = w1[idx];
        wt[2 * SZ + o] = w2[idx];
        wt[3 * SZ + o] = w3[idx];
    }
}

__global__ void transpose_kernel(const float* __restrict__ in, float* __restrict__ out,
                                 int R, int Cc)
{
    __shared__ float tile[32][33];
    const int bc = blockIdx.z;
    const int c0 = blockIdx.x * 32;
    const int r0 = blockIdx.y * 32;
    const float* ip = in + (size_t)bc * R * Cc;
    float* op = out + (size_t)bc * R * Cc;
    const int tx = threadIdx.x, ty = threadIdx.y;

    for (int i = ty; i < 32; i += 8) {
        int r = r0 + i, c = c0 + tx;
        if (r < R && c < Cc) tile[i][tx] = ip[(size_t)r * Cc + c];
    }
    __syncthreads();
    for (int i = ty; i < 32; i += 8) {
        int c = c0 + i, r = r0 + tx;
        if (c < Cc && r < R) op[(size_t)c * R + r] = tile[tx][i];
    }
}

extern "C" void kernel_launch(void* const* d_in, const int* in_sizes, int n_in,
                              void* d_out, int out_size)
{
    const float* x   = (const float*)d_in[0];
    const float* w_d = (const float*)d_in[1];
    const float* b_d = (const float*)d_in[2];
    const float* w_u = (const float*)d_in[3];
    const float* b_u = (const float*)d_in[4];
    const float* w_r = (const float*)d_in[5];
    const float* b_r = (const float*)d_in[6];
    const float* w_l = (const float*)d_in[7];
    const float* b_l = (const float*)d_in[8];
    float* out = (float*)d_out;

    float* T = nullptr;
    cudaGetSymbolAddress((void**)&T, g_T);
    float* Wt = nullptr;
    cudaGetSymbolAddress((void**)&Wt, g_Wt);
    const size_t SZ = (size_t)CC * CC * KK;
    float* wt_d = Wt;
    float* wt_u = Wt + SZ;
    float* wt_r = Wt + 2 * SZ;
    float* wt_l = Wt + 3 * SZ;

    dummy_kernel<<<1, 32>>>();
    dummy_kernel<<<1, 32>>>();

    const int WG = (CC * CC * KK + 255) / 256;
    prep_w4<<<WG, 256>>>(w_d, w_u, w_r, w_l, Wt);

    const size_t nbytes = (size_t)BB * CC * HH * WW * sizeof(float);
    cudaMemcpyAsync(out, x, nbytes, cudaMemcpyDeviceToDevice, 0);

    // H passes: cluster-4, 320 thr, smem 202752 B.
    {
        constexpr int SMEM_H = (CC * KK * 32 + 2 * 2 * 32 * 108) * 4;
        cudaFuncSetAttribute(pass_kernel<WW, HH, 8, 10, 10, 2>,
                             cudaFuncAttributeMaxDynamicSharedMemorySize, SMEM_H);
        dim3 g(4, 32);
        pass_kernel<WW, HH, 8, 10, 10, 2><<<g, 320, SMEM_H>>>(out, wt_d, b_d, 1, HH - 1, +1);
        pass_kernel<WW, HH, 8, 10, 10, 2><<<g, 320, SMEM_H>>>(out, wt_u, b_u, HH - 2, HH - 2, -1);
    }

    {
        dim3 tb(32, 8);
        dim3 tg((WW + 31) / 32, (HH + 31) / 32, BB * CC);
        transpose_kernel<<<tg, tb>>>(out, T, HH, WW);
    }

    // W passes: cluster-4 DSMEM kernel, 384 thr, smem 229376 B.
    {
        constexpr int SMEM_W = (CC * KK * 32 + 2 * CC * W_ROW + 3 * 2304 + 2304) * 4;
        cudaFuncSetAttribute(wpass_kernel,
                             cudaFuncAttributeMaxDynamicSharedMemorySize, SMEM_W);
        dim3 g(4, 32);
        wpass_kernel<<<g, W_NT, SMEM_W>>>(T, wt_r, b_r, 1, WW - 1, +1);
        wpass_kernel<<<g, W_NT, SMEM_W>>>(T, wt_l, b_l, WW - 2, WW - 2, -1);
    }

    {
        dim3 tb(32, 8);
        dim3 tg((HH + 31) / 32, (WW + 31) / 32, BB * CC);
        transpose_kernel<<<tg, tb>>>(T, out, WW, HH);
    }
}

// round 14
// speedup vs baseline: 1.5921x; 1.5921x over previous
#include <cuda_runtime.h>
#include <cuda_bf16.h>

// SpatialConv SCNN, GB300 sm_103a.
// R14: exact revert to R12 (best measured: 6533us). H pass: cp.async staging
// + spin group barrier. W pass: cluster-4 DSMEM push of the recurrence column.

#define BB 64
#define CC 128
#define HH 36
#define WW 100
#define KK 9

typedef unsigned long long u64;

__device__ float g_T[(size_t)BB * CC * WW * HH];
__device__ float g_Wt[4][CC * CC * KK];            // [ci*9+k][co]

struct __align__(128) BarLine { u64 cnt; u64 rel; u64 pad[14]; };
__device__ BarLine g_bar[32];

__device__ __forceinline__ void ffma2(u64& d, u64 a, u64 b) {
    asm("fma.rn.f32x2 %0, %1, %2, %0;" : "+l"(d) : "l"(a), "l"(b));
}
__device__ __forceinline__ u64 pack2(float a, float b) {
    u64 r; asm("mov.b64 %0, {%1, %2};" : "=l"(r) : "f"(a), "f"(b)); return r;
}
__device__ __forceinline__ void unpack2(u64 v, float& a, float& b) {
    asm("mov.b64 {%0, %1}, %2;" : "=f"(a), "=f"(b) : "l"(v));
}
__device__ __forceinline__ unsigned smem_u32(const void* p) {
    unsigned a;
    asm("{ .reg .u64 t; cvta.to.shared.u64 t, %1; cvt.u32.u64 %0, t; }"
        : "=r"(a) : "l"(p));
    return a;
}
__device__ __forceinline__ unsigned mapa_u32(unsigned laddr, unsigned rank) {
    unsigned r;
    asm("mapa.shared::cluster.u32 %0, %1, %2;" : "=r"(r) : "r"(laddr), "r"(rank));
    return r;
}
__device__ __forceinline__ void st_cluster64(unsigned addr, u64 v) {
    asm volatile("st.shared::cluster.u64 [%0], %1;" :: "r"(addr), "l"(v) : "memory");
}
__device__ __forceinline__ void cluster_sync() {
    asm volatile("barrier.cluster.arrive.aligned;" ::: "memory");
    asm volatile("barrier.cluster.wait.aligned;" ::: "memory");
}
__device__ __forceinline__ void cp_async16(unsigned dst, const void* src, int srcsize) {
    asm volatile("cp.async.ca.shared.global [%0], [%1], 16, %2;"
                 :: "r"(dst), "l"(src), "r"(srcsize) : "memory");
}
#define CP_COMMIT() asm volatile("cp.async.commit_group;" ::: "memory")
#define CP_WAIT0()  asm volatile("cp.async.wait_group 0;" ::: "memory")

template <int NB>
__device__ __forceinline__ void group_barrier(int gid) {
    __syncthreads();
    if (threadIdx.x == 0) {
        __threadfence();
        u64 arrived = atomicAdd(&g_bar[gid].cnt, 1ULL);
        u64 epoch = arrived / NB;
        if (arrived % NB == (u64)(NB - 1)) {
            atomicAdd(&g_bar[gid].rel, 1ULL);
        } else {
            unsigned spins = 0;
            while (*(volatile u64*)&g_bar[gid].rel <= epoch) {
                if ((++spins & 63u) == 0) __nanosleep(32);
                if (spins > (1u << 26)) break;
            }
        }
        __threadfence();
    }
    __syncthreads();
}

__global__ void dummy_kernel() {}

// ================= H pass: cp.async staging (R11/R12) ======================
template <int L, int S, int CP, int LG, int NL, int CIS>
__global__ __launch_bounds__(2 * CP * LG * CIS, 1)
void pass_kernel(float* __restrict__ buf,
                 const float* __restrict__ wt, const float* __restrict__ bias,
                 int s_begin, int nsteps, int dir)
{
    constexpr int CO_TILE = 4 * CP;
    constexpr int WIN  = LG * NL + 8;
    constexpr int WINQ = WIN / 4;
    constexpr int NT   = 2 * CP * LG * CIS;
    constexpr int CIC  = 32;
    constexpr int NCHUNK = CC / CIC;
    constexpr int RPC  = CIC / CIS;
    static_assert(LG * NL == L, "");
    static_assert((NL & 1) == 0 && (L & 3) == 0 && (WIN & 3) == 0, "");

    extern __shared__ __align__(16) char smem_raw[];
    float* w_all = (float*)smem_raw;
    float* in_d  = w_all + CC * KK * CO_TILE;
    float* red   = in_d;

    const int tid  = threadIdx.x;
    const int lg   = tid % LG;
    const int cp   = (tid / LG) % CP;
    const int bsel = (tid / (LG * CP)) % 2;
    const int cis  = tid / (LG * CP * 2);
    const int b0   = blockIdx.y * 2;
    const int co_base = blockIdx.x * CO_TILE;
    const int gid  = blockIdx.y;
    const unsigned in_u32 = smem_u32(in_d);

    for (int idx = tid; idx < CC * KK * CO_TILE; idx += NT)
        w_all[idx] = wt[(size_t)(idx / CO_TILE) * CC + co_base + (idx % CO_TILE)];

    u64 bias01, bias23;
    {
        float v0 = bias[co_base + 4 * cp + 0];
        float v1 = bias[co_base + 4 * cp + 1];
        float v2 = bias[co_base + 4 * cp + 2];
        float v3 = bias[co_base + 4 * cp + 3];
        bias01 = (cis == 0) ? pack2(v0, v1) : 0ull;
        bias23 = (cis == 0) ? pack2(v2, v3) : 0ull;
    }
    __syncthreads();

    for (int it = 0; it < nsteps; it++) {
        const int s_dst = s_begin + it * dir;
        const int s_src = s_dst - dir;

        auto issue_chunk = [&](int cc, int pb) {
            for (int idx = tid; idx < 2 * CIC * WINQ; idx += NT) {
                int bs = idx / (CIC * WINQ);
                int rem = idx % (CIC * WINQ);
                int r = rem / WINQ, q = rem % WINQ;
                int ci = (r / RPC) * (CC / CIS) + cc * RPC + (r % RPC);
                int gl4 = q * 4 - 4;
                int ssz = (gl4 < 0 || gl4 + 3 >= L) ? 0 : 16;
                int gls = gl4 < 0 ? 0 : gl4;
                const float* src =
                    &buf[((size_t)((b0 + bs) * CC + ci) * S + s_src) * L + gls];
                unsigned dst = in_u32 +
                    (unsigned)((((pb * 2 + bs) * CIC + r) * WIN + q * 4) * 4);
                cp_async16(dst, src, ssz);
            }
            CP_COMMIT();
        };

        issue_chunk(0, 0);
        CP_WAIT0();
        __syncthreads();

        u64 acc0[NL], acc1[NL];
#pragma unroll
        for (int j = 0; j < NL; j++) { acc0[j] = bias01; acc1[j] = bias23; }

        for (int c = 0; c < NCHUNK; c++) {
            const int p = c & 1;
            if (c < NCHUNK - 1) issue_chunk(c + 1, p ^ 1);

#pragma unroll 2
            for (int rI = 0; rI < RPC; rI++) {
                const int r = cis * RPC + rI;
                const int ci = cis * (CC / CIS) + c * RPC + rI;
                const float* srow = &in_d[((p * 2 + bsel) * CIC + r) * WIN + lg * NL];
                u64 xx[NL + 8];
#pragma unroll
                for (int t = 0; t < (NL + 8) / 2; t++) {
                    float2 f = ((const float2*)srow)[t];
                    xx[2 * t + 0] = pack2(f.x, f.x);
                    xx[2 * t + 1] = pack2(f.y, f.y);
                }
                const float* wr = &w_all[(size_t)(ci * KK) * CO_TILE + 4 * cp];
#pragma unroll
                for (int k = 0; k < KK; k++) {
                    ulonglong2 wv = *(const ulonglong2*)(wr + k * CO_TILE);
#pragma unroll
                    for (int j = 0; j < NL; j++) {
                        ffma2(acc0[j], wv.x, xx[j + k]);
                        ffma2(acc1[j], wv.y, xx[j + k]);
                    }
                }
            }
            if (c < NCHUNK - 1) {
                CP_WAIT0();
                __syncthreads();
            }
        }
        __syncthreads();

        if (CIS > 1) {
            if (cis > 0) {
                float* pr = &red[((size_t)(cis - 1) * 2 + bsel) * CO_TILE * L];
#pragma unroll
                for (int j = 0; j < NL; j++) {
                    int l = lg * NL + j;
                    float a, bb, cv, d;
                    unpack2(acc0[j], a, bb); unpack2(acc1[j], cv, d);
                    pr[(4 * cp + 0) * L + l] = a;
                    pr[(4 * cp + 1) * L + l] = bb;
                    pr[(4 * cp + 2) * L + l] = cv;
                    pr[(4 * cp + 3) * L + l] = d;
                }
            }
            __syncthreads();
        }

        if (cis == 0) {
#pragma unroll
            for (int j = 0; j < NL; j++) {
                int l = lg * NL + j;
                float a, bb, cv, d;
                unpack2(acc0[j], a, bb); unpack2(acc1[j], cv, d);
#pragma unroll
                for (int c2 = 1; c2 < CIS; c2++) {
                    const float* pr = &red[((size_t)(c2 - 1) * 2 + bsel) * CO_TILE * L];
                    a  += pr[(4 * cp + 0) * L + l];
                    bb += pr[(4 * cp + 1) * L + l];
                    cv += pr[(4 * cp + 2) * L + l];
                    d  += pr[(4 * cp + 3) * L + l];
                }
                size_t base = ((size_t)((b0 + bsel) * CC + co_base + 4 * cp) * S + s_dst) * L + l;
                buf[base + 0 * S * L] += fmaxf(a, 0.f);
                buf[base + 1 * S * L] += fmaxf(bb, 0.f);
                buf[base + 2 * S * L] += fmaxf(cv, 0.f);
                buf[base + 3 * S * L] += fmaxf(d, 0.f);
            }
        }

        group_barrier<4>(gid);
    }
}

// ============ W pass: cluster-4, DSMEM push of the new column ==============
#define W_L   36
#define W_S   100
#define W_ROW 44
#define W_NT  384

__global__ __launch_bounds__(W_NT, 1) __cluster_dims__(4, 1, 1)
void wpass_kernel(float* __restrict__ buf,
                  const float* __restrict__ wt, const float* __restrict__ bias,
                  int s_begin, int nsteps, int dir)
{
    extern __shared__ __align__(16) char smem_raw[];
    float* w_all  = (float*)smem_raw;                 // 128*9*32
    float* state  = w_all + CC * KK * 32;             // [2][128][44]
    float* red    = state + 2 * CC * W_ROW;           // 3 * 2304
    float* newcol = red + 3 * 2304;                   // [2][32][36]

    const int tid  = threadIdx.x;
    const int lg   = tid % 3;
    const int cp   = (tid / 3) % 16;
    const int bsel = (tid / 48) % 2;
    const int cis  = tid / 96;
    const int b0   = blockIdx.y * 2;
    const int co_base = blockIdx.x * 32;              // blockIdx.x == cluster rank
    const unsigned state_u32 = smem_u32(state);

    for (int idx = tid; idx < CC * KK * 32; idx += W_NT)
        w_all[idx] = wt[(size_t)(idx / 32) * CC + co_base + (idx % 32)];

    for (int idx = tid; idx < 2 * CC * W_ROW; idx += W_NT) state[idx] = 0.f;
    __syncthreads();
    {
        const int s0 = s_begin - dir;
        for (int idx = tid; idx < 2 * CC * 9; idx += W_NT) {
            int bs = idx / (CC * 9);
            int r  = idx % (CC * 9);
            int ci = r / 9, q = r % 9;
            const float4* src = (const float4*)
                &buf[(((size_t)(b0 + bs) * CC + ci) * W_S + s0) * W_L];
            ((float4*)&state[(bs * CC + ci) * W_ROW + 4])[q] = src[q];
        }
    }

    const u64 biasp = (cis == 0)
        ? pack2(bias[co_base + 2 * cp], bias[co_base + 2 * cp + 1]) : 0ull;
    __syncthreads();

    for (int it = 0; it < nsteps; it++) {
        const int s_dst = s_begin + it * dir;

        float4 og[6];
        if (cis == 0) {
#pragma unroll
            for (int q = 0; q < 2; q++) {
                const float4* src = (const float4*)
                    &buf[(((size_t)(b0 + bsel) * CC + co_base + 2 * cp + q) * W_S + s_dst)
                         * W_L + lg * 12];
#pragma unroll
                for (int t = 0; t < 3; t++) og[q * 3 + t] = src[t];
            }
        }

        u64 acc[12];
#pragma unroll
        for (int j = 0; j < 12; j++) acc[j] = biasp;

#pragma unroll 2
        for (int i = 0; i < 32; i++) {
            const int ci = cis * 32 + i;
            const float* srow = &state[(bsel * CC + ci) * W_ROW + lg * 12];
            u64 xx[20];
#pragma unroll
            for (int t = 0; t < 5; t++) {
                float4 f = ((const float4*)srow)[t];
                xx[4 * t + 0] = pack2(f.x, f.x);
                xx[4 * t + 1] = pack2(f.y, f.y);
                xx[4 * t + 2] = pack2(f.z, f.z);
                xx[4 * t + 3] = pack2(f.w, f.w);
            }
            const float* wr = &w_all[(size_t)(ci * KK) * 32 + 2 * cp];
#pragma unroll
            for (int k = 0; k < KK; k++) {
                u64 wv = *(const u64*)(wr + k * 32);
#pragma unroll
                for (int j = 0; j < 12; j++) ffma2(acc[j], wv, xx[j + k]);
            }
        }
        __syncthreads();   // own CTA's state reads done; red safe

        if (cis > 0) {
            float* pr = &red[(size_t)(cis - 1) * 2304];
#pragma unroll
            for (int j = 0; j < 12; j++) {
                int l = lg * 12 + j;
                float a, b2; unpack2(acc[j], a, b2);
                pr[(bsel * 32 + 2 * cp + 0) * W_L + l] = a;
                pr[(bsel * 32 + 2 * cp + 1) * W_L + l] = b2;
            }
        }
        __syncthreads();

        if (cis == 0) {
            float fin[24];
#pragma unroll
            for (int j = 0; j < 12; j++) {
                int l = lg * 12 + j;
                int f0 = (bsel * 32 + 2 * cp + 0) * W_L + l;
                int f1 = (bsel * 32 + 2 * cp + 1) * W_L + l;
                float a, b2; unpack2(acc[j], a, b2);
                a  += red[f0] + red[2304 + f0] + red[4608 + f0];
                b2 += red[f1] + red[2304 + f1] + red[4608 + f1];
                fin[j]      = ((const float*)og)[j]      + fmaxf(a, 0.f);
                fin[12 + j] = ((const float*)og)[12 + j] + fmaxf(b2, 0.f);
            }
#pragma unroll
            for (int q = 0; q < 2; q++) {
                float4* dst = (float4*)
                    &buf[(((size_t)(b0 + bsel) * CC + co_base + 2 * cp + q) * W_S + s_dst)
                         * W_L + lg * 12];
                float4* nst = (float4*)
                    &newcol[(bsel * 32 + 2 * cp + q) * W_L + lg * 12];
#pragma unroll
                for (int t = 0; t < 3; t++) {
                    float4 v = ((const float4*)fin)[q * 3 + t];
                    dst[t] = v;
                    nst[t] = v;
                }
            }
        }
        __syncthreads();   // newcol staged

        cluster_sync();    // all CTAs done reading state

        for (int idx = tid; idx < 2 * 32 * (W_L / 2); idx += W_NT) {
            int bs = idx / (32 * 18);
            int r  = idx % (32 * 18);
            int co = r / 18, q = r % 18;
            u64 v = ((const u64*)&newcol[(bs * 32 + co) * W_L])[q];
            unsigned loff = state_u32 +
                (unsigned)(((bs * CC + co_base + co) * W_ROW + 4) * 4 + q * 8);
#pragma unroll
            for (unsigned rk = 0; rk < 4; rk++)
                st_cluster64(mapa_u32(loff, rk), v);
        }

        cluster_sync();    // pushes visible cluster-wide
    }
}

// [co][ci][k] -> [ci*9+k][co] for all 4 sets
__global__ void prep_w4(const float* __restrict__ w0, const float* __restrict__ w1,
                        const float* __restrict__ w2, const float* __restrict__ w3,
                        float* __restrict__ wt)
{
    int idx = blockIdx.x * 256 + threadIdx.x;
    if (idx < CC * CC * KK) {
        int co = idx / (CC * KK);
        int rem = idx % (CC * KK);
        int ci = rem / KK, k = rem % KK;
        size_t o = ((size_t)ci * KK + k) * CC + co;
        const size_t SZ = (size_t)CC * CC * KK;
        wt[o] = w0[idx];
        wt[SZ + o] = w1[idx];
        wt[2 * SZ + o] = w2[idx];
        wt[3 * SZ + o] = w3[idx];
    }
}

__global__ void transpose_kernel(const float* __restrict__ in, float* __restrict__ out,
                                 int R, int Cc)
{
    __shared__ float tile[32][33];
    const int bc = blockIdx.z;
    const int c0 = blockIdx.x * 32;
    const int r0 = blockIdx.y * 32;
    const float* ip = in + (size_t)bc * R * Cc;
    float* op = out + (size_t)bc * R * Cc;
    const int tx = threadIdx.x, ty = threadIdx.y;

    for (int i = ty; i < 32; i += 8) {
        int r = r0 + i, c = c0 + tx;
        if (r < R && c < Cc) tile[i][tx] = ip[(size_t)r * Cc + c];
    }
    __syncthreads();
    for (int i = ty; i < 32; i += 8) {
        int c = c0 + i, r = r0 + tx;
        if (c < Cc && r < R) op[(size_t)c * R + r] = tile[tx][i];
    }
}

extern "C" void kernel_launch(void* const* d_in, const int* in_sizes, int n_in,
                              void* d_out, int out_size)
{
    const float* x   = (const float*)d_in[0];
    const float* w_d = (const float*)d_in[1];
    const float* b_d = (const float*)d_in[2];
    const float* w_u = (const float*)d_in[3];
    const float* b_u = (const float*)d_in[4];
    const float* w_r = (const float*)d_in[5];
    const float* b_r = (const float*)d_in[6];
    const float* w_l = (const float*)d_in[7];
    const float* b_l = (const float*)d_in[8];
    float* out = (float*)d_out;

    float* T = nullptr;
    cudaGetSymbolAddress((void**)&T, g_T);
    float* Wt = nullptr;
    cudaGetSymbolAddress((void**)&Wt, g_Wt);
    const size_t SZ = (size_t)CC * CC * KK;
    float* wt_d = Wt;
    float* wt_u = Wt + SZ;
    float* wt_r = Wt + 2 * SZ;
    float* wt_l = Wt + 3 * SZ;

    dummy_kernel<<<1, 32>>>();
    dummy_kernel<<<1, 32>>>();

    const int WG = (CC * CC * KK + 255) / 256;
    prep_w4<<<WG, 256>>>(w_d, w_u, w_r, w_l, Wt);

    const size_t nbytes = (size_t)BB * CC * HH * WW * sizeof(float);
    cudaMemcpyAsync(out, x, nbytes, cudaMemcpyDeviceToDevice, 0);

    // H passes: 320 thr, smem 202752 B.
    {
        constexpr int SMEM_H = (CC * KK * 32 + 2 * 2 * 32 * 108) * 4;
        cudaFuncSetAttribute(pass_kernel<WW, HH, 8, 10, 10, 2>,
                             cudaFuncAttributeMaxDynamicSharedMemorySize, SMEM_H);
        dim3 g(4, 32);
        pass_kernel<WW, HH, 8, 10, 10, 2><<<g, 320, SMEM_H>>>(out, wt_d, b_d, 1, HH - 1, +1);
        pass_kernel<WW, HH, 8, 10, 10, 2><<<g, 320, SMEM_H>>>(out, wt_u, b_u, HH - 2, HH - 2, -1);
    }

    {
        dim3 tb(32, 8);
        dim3 tg((WW + 31) / 32, (HH + 31) / 32, BB * CC);
        transpose_kernel<<<tg, tb>>>(out, T, HH, WW);
    }

    // W passes: cluster-4 DSMEM kernel, 384 thr, smem 229376 B.
    {
        constexpr int SMEM_W = (CC * KK * 32 + 2 * CC * W_ROW + 3 * 2304 + 2304) * 4;
        cudaFuncSetAttribute(wpass_kernel,
                             cudaFuncAttributeMaxDynamicSharedMemorySize, SMEM_W);
        dim3 g(4, 32);
        wpass_kernel<<<g, W_NT, SMEM_W>>>(T, wt_r, b_r, 1, WW - 1, +1);
        wpass_kernel<<<g, W_NT, SMEM_W>>>(T, wt_l, b_l, WW - 2, WW - 2, -1);
    }

    {
        dim3 tb(32, 8);
        dim3 tg((HH + 31) / 32, (WW + 31) / 32, BB * CC);
        transpose_kernel<<<tg, tb>>>(T, out, WW, HH);
    }
}

// round 15
// speedup vs baseline: 1.6423x; 1.0315x over previous
#include <cuda_runtime.h>
#include <cuda_bf16.h>

// SpatialConv SCNN, GB300 sm_103a.
// R15: R14 base + (1) slice-resident transpose kernels (1 CTA per 36x100
// slice, padded-SMEM, fully coalesced both sides), (2) H-pass epilogue
// residual prefetched into registers (STG-only epilogue).

#define BB 64
#define CC 128
#define HH 36
#define WW 100
#define KK 9

typedef unsigned long long u64;

__device__ float g_T[(size_t)BB * CC * WW * HH];
__device__ float g_Wt[4][CC * CC * KK];            // [ci*9+k][co]

struct __align__(128) BarLine { u64 cnt; u64 rel; u64 pad[14]; };
__device__ BarLine g_bar[32];

__device__ __forceinline__ void ffma2(u64& d, u64 a, u64 b) {
    asm("fma.rn.f32x2 %0, %1, %2, %0;" : "+l"(d) : "l"(a), "l"(b));
}
__device__ __forceinline__ u64 pack2(float a, float b) {
    u64 r; asm("mov.b64 %0, {%1, %2};" : "=l"(r) : "f"(a), "f"(b)); return r;
}
__device__ __forceinline__ void unpack2(u64 v, float& a, float& b) {
    asm("mov.b64 {%0, %1}, %2;" : "=f"(a), "=f"(b) : "l"(v));
}
__device__ __forceinline__ unsigned smem_u32(const void* p) {
    unsigned a;
    asm("{ .reg .u64 t; cvta.to.shared.u64 t, %1; cvt.u32.u64 %0, t; }"
        : "=r"(a) : "l"(p));
    return a;
}
__device__ __forceinline__ unsigned mapa_u32(unsigned laddr, unsigned rank) {
    unsigned r;
    asm("mapa.shared::cluster.u32 %0, %1, %2;" : "=r"(r) : "r"(laddr), "r"(rank));
    return r;
}
__device__ __forceinline__ void st_cluster64(unsigned addr, u64 v) {
    asm volatile("st.shared::cluster.u64 [%0], %1;" :: "r"(addr), "l"(v) : "memory");
}
__device__ __forceinline__ void cluster_sync() {
    asm volatile("barrier.cluster.arrive.aligned;" ::: "memory");
    asm volatile("barrier.cluster.wait.aligned;" ::: "memory");
}
__device__ __forceinline__ void cp_async16(unsigned dst, const void* src, int srcsize) {
    asm volatile("cp.async.ca.shared.global [%0], [%1], 16, %2;"
                 :: "r"(dst), "l"(src), "r"(srcsize) : "memory");
}
#define CP_COMMIT() asm volatile("cp.async.commit_group;" ::: "memory")
#define CP_WAIT0()  asm volatile("cp.async.wait_group 0;" ::: "memory")

template <int NB>
__device__ __forceinline__ void group_barrier(int gid) {
    __syncthreads();
    if (threadIdx.x == 0) {
        __threadfence();
        u64 arrived = atomicAdd(&g_bar[gid].cnt, 1ULL);
        u64 epoch = arrived / NB;
        if (arrived % NB == (u64)(NB - 1)) {
            atomicAdd(&g_bar[gid].rel, 1ULL);
        } else {
            unsigned spins = 0;
            while (*(volatile u64*)&g_bar[gid].rel <= epoch) {
                if ((++spins & 63u) == 0) __nanosleep(32);
                if (spins > (1u << 26)) break;
            }
        }
        __threadfence();
    }
    __syncthreads();
}

__global__ void dummy_kernel() {}

// ================= H pass: cp.async staging + og prefetch ==================
template <int L, int S, int CP, int LG, int NL, int CIS>
__global__ __launch_bounds__(2 * CP * LG * CIS, 1)
void pass_kernel(float* __restrict__ buf,
                 const float* __restrict__ wt, const float* __restrict__ bias,
                 int s_begin, int nsteps, int dir)
{
    constexpr int CO_TILE = 4 * CP;
    constexpr int WIN  = LG * NL + 8;
    constexpr int WINQ = WIN / 4;
    constexpr int NT   = 2 * CP * LG * CIS;
    constexpr int CIC  = 32;
    constexpr int NCHUNK = CC / CIC;
    constexpr int RPC  = CIC / CIS;
    static_assert(LG * NL == L, "");
    static_assert((NL & 1) == 0 && (L & 3) == 0 && (WIN & 3) == 0, "");

    extern __shared__ __align__(16) char smem_raw[];
    float* w_all = (float*)smem_raw;
    float* in_d  = w_all + CC * KK * CO_TILE;
    float* red   = in_d;

    const int tid  = threadIdx.x;
    const int lg   = tid % LG;
    const int cp   = (tid / LG) % CP;
    const int bsel = (tid / (LG * CP)) % 2;
    const int cis  = tid / (LG * CP * 2);
    const int b0   = blockIdx.y * 2;
    const int co_base = blockIdx.x * CO_TILE;
    const int gid  = blockIdx.y;
    const unsigned in_u32 = smem_u32(in_d);

    for (int idx = tid; idx < CC * KK * CO_TILE; idx += NT)
        w_all[idx] = wt[(size_t)(idx / CO_TILE) * CC + co_base + (idx % CO_TILE)];

    u64 bias01, bias23;
    {
        float v0 = bias[co_base + 4 * cp + 0];
        float v1 = bias[co_base + 4 * cp + 1];
        float v2 = bias[co_base + 4 * cp + 2];
        float v3 = bias[co_base + 4 * cp + 3];
        bias01 = (cis == 0) ? pack2(v0, v1) : 0ull;
        bias23 = (cis == 0) ? pack2(v2, v3) : 0ull;
    }
    __syncthreads();

    for (int it = 0; it < nsteps; it++) {
        const int s_dst = s_begin + it * dir;
        const int s_src = s_dst - dir;

        auto issue_chunk = [&](int cc, int pb) {
            for (int idx = tid; idx < 2 * CIC * WINQ; idx += NT) {
                int bs = idx / (CIC * WINQ);
                int rem = idx % (CIC * WINQ);
                int r = rem / WINQ, q = rem % WINQ;
                int ci = (r / RPC) * (CC / CIS) + cc * RPC + (r % RPC);
                int gl4 = q * 4 - 4;
                int ssz = (gl4 < 0 || gl4 + 3 >= L) ? 0 : 16;
                int gls = gl4 < 0 ? 0 : gl4;
                const float* src =
                    &buf[((size_t)((b0 + bs) * CC + ci) * S + s_src) * L + gls];
                unsigned dst = in_u32 +
                    (unsigned)((((pb * 2 + bs) * CIC + r) * WIN + q * 4) * 4);
                cp_async16(dst, src, ssz);
            }
            CP_COMMIT();
        };

        issue_chunk(0, 0);

        // Prefetch epilogue residual (cis0 only) — overlaps the chunk-0 wait.
        float og[4 * NL];
        if (cis == 0) {
#pragma unroll
            for (int q = 0; q < 4; q++) {
                const float2* src = (const float2*)
                    &buf[((size_t)((b0 + bsel) * CC + co_base + 4 * cp + q) * S + s_dst)
                         * L + lg * NL];
#pragma unroll
                for (int t = 0; t < NL / 2; t++)
                    ((float2*)og)[q * (NL / 2) + t] = src[t];
            }
        }

        CP_WAIT0();
        __syncthreads();

        u64 acc0[NL], acc1[NL];
#pragma unroll
        for (int j = 0; j < NL; j++) { acc0[j] = bias01; acc1[j] = bias23; }

        for (int c = 0; c < NCHUNK; c++) {
            const int p = c & 1;
            if (c < NCHUNK - 1) issue_chunk(c + 1, p ^ 1);

#pragma unroll 2
            for (int rI = 0; rI < RPC; rI++) {
                const int r = cis * RPC + rI;
                const int ci = cis * (CC / CIS) + c * RPC + rI;
                const float* srow = &in_d[((p * 2 + bsel) * CIC + r) * WIN + lg * NL];
                u64 xx[NL + 8];
#pragma unroll
                for (int t = 0; t < (NL + 8) / 2; t++) {
                    float2 f = ((const float2*)srow)[t];
                    xx[2 * t + 0] = pack2(f.x, f.x);
                    xx[2 * t + 1] = pack2(f.y, f.y);
                }
                const float* wr = &w_all[(size_t)(ci * KK) * CO_TILE + 4 * cp];
#pragma unroll
                for (int k = 0; k < KK; k++) {
                    ulonglong2 wv = *(const ulonglong2*)(wr + k * CO_TILE);
#pragma unroll
                    for (int j = 0; j < NL; j++) {
                        ffma2(acc0[j], wv.x, xx[j + k]);
                        ffma2(acc1[j], wv.y, xx[j + k]);
                    }
                }
            }
            if (c < NCHUNK - 1) {
                CP_WAIT0();
                __syncthreads();
            }
        }
        __syncthreads();

        if (CIS > 1) {
            if (cis > 0) {
                float* pr = &red[((size_t)(cis - 1) * 2 + bsel) * CO_TILE * L];
#pragma unroll
                for (int j = 0; j < NL; j++) {
                    int l = lg * NL + j;
                    float a, bb, cv, d;
                    unpack2(acc0[j], a, bb); unpack2(acc1[j], cv, d);
                    pr[(4 * cp + 0) * L + l] = a;
                    pr[(4 * cp + 1) * L + l] = bb;
                    pr[(4 * cp + 2) * L + l] = cv;
                    pr[(4 * cp + 3) * L + l] = d;
                }
            }
            __syncthreads();
        }

        if (cis == 0) {
#pragma unroll
            for (int j = 0; j < NL; j++) {
                int l = lg * NL + j;
                float a, bb, cv, d;
                unpack2(acc0[j], a, bb); unpack2(acc1[j], cv, d);
#pragma unroll
                for (int c2 = 1; c2 < CIS; c2++) {
                    const float* pr = &red[((size_t)(c2 - 1) * 2 + bsel) * CO_TILE * L];
                    a  += pr[(4 * cp + 0) * L + l];
                    bb += pr[(4 * cp + 1) * L + l];
                    cv += pr[(4 * cp + 2) * L + l];
                    d  += pr[(4 * cp + 3) * L + l];
                }
                size_t base = ((size_t)((b0 + bsel) * CC + co_base + 4 * cp) * S + s_dst) * L + l;
                buf[base + 0 * S * L] = og[0 * NL + j] + fmaxf(a, 0.f);
                buf[base + 1 * S * L] = og[1 * NL + j] + fmaxf(bb, 0.f);
                buf[base + 2 * S * L] = og[2 * NL + j] + fmaxf(cv, 0.f);
                buf[base + 3 * S * L] = og[3 * NL + j] + fmaxf(d, 0.f);
            }
        }

        group_barrier<4>(gid);
    }
}

// ============ W pass: cluster-4, DSMEM push (R12/R14, unchanged) ===========
#define W_L   36
#define W_S   100
#define W_ROW 44
#define W_NT  384

__global__ __launch_bounds__(W_NT, 1) __cluster_dims__(4, 1, 1)
void wpass_kernel(float* __restrict__ buf,
                  const float* __restrict__ wt, const float* __restrict__ bias,
                  int s_begin, int nsteps, int dir)
{
    extern __shared__ __align__(16) char smem_raw[];
    float* w_all  = (float*)smem_raw;                 // 128*9*32
    float* state  = w_all + CC * KK * 32;             // [2][128][44]
    float* red    = state + 2 * CC * W_ROW;           // 3 * 2304
    float* newcol = red + 3 * 2304;                   // [2][32][36]

    const int tid  = threadIdx.x;
    const int lg   = tid % 3;
    const int cp   = (tid / 3) % 16;
    const int bsel = (tid / 48) % 2;
    const int cis  = tid / 96;
    const int b0   = blockIdx.y * 2;
    const int co_base = blockIdx.x * 32;
    const unsigned state_u32 = smem_u32(state);

    for (int idx = tid; idx < CC * KK * 32; idx += W_NT)
        w_all[idx] = wt[(size_t)(idx / 32) * CC + co_base + (idx % 32)];

    for (int idx = tid; idx < 2 * CC * W_ROW; idx += W_NT) state[idx] = 0.f;
    __syncthreads();
    {
        const int s0 = s_begin - dir;
        for (int idx = tid; idx < 2 * CC * 9; idx += W_NT) {
            int bs = idx / (CC * 9);
            int r  = idx % (CC * 9);
            int ci = r / 9, q = r % 9;
            const float4* src = (const float4*)
                &buf[(((size_t)(b0 + bs) * CC + ci) * W_S + s0) * W_L];
            ((float4*)&state[(bs * CC + ci) * W_ROW + 4])[q] = src[q];
        }
    }

    const u64 biasp = (cis == 0)
        ? pack2(bias[co_base + 2 * cp], bias[co_base + 2 * cp + 1]) : 0ull;
    __syncthreads();

    for (int it = 0; it < nsteps; it++) {
        const int s_dst = s_begin + it * dir;

        float4 og[6];
        if (cis == 0) {
#pragma unroll
            for (int q = 0; q < 2; q++) {
                const float4* src = (const float4*)
                    &buf[(((size_t)(b0 + bsel) * CC + co_base + 2 * cp + q) * W_S + s_dst)
                         * W_L + lg * 12];
#pragma unroll
                for (int t = 0; t < 3; t++) og[q * 3 + t] = src[t];
            }
        }

        u64 acc[12];
#pragma unroll
        for (int j = 0; j < 12; j++) acc[j] = biasp;

#pragma unroll 2
        for (int i = 0; i < 32; i++) {
            const int ci = cis * 32 + i;
            const float* srow = &state[(bsel * CC + ci) * W_ROW + lg * 12];
            u64 xx[20];
#pragma unroll
            for (int t = 0; t < 5; t++) {
                float4 f = ((const float4*)srow)[t];
                xx[4 * t + 0] = pack2(f.x, f.x);
                xx[4 * t + 1] = pack2(f.y, f.y);
                xx[4 * t + 2] = pack2(f.z, f.z);
                xx[4 * t + 3] = pack2(f.w, f.w);
            }
            const float* wr = &w_all[(size_t)(ci * KK) * 32 + 2 * cp];
#pragma unroll
            for (int k = 0; k < KK; k++) {
                u64 wv = *(const u64*)(wr + k * 32);
#pragma unroll
                for (int j = 0; j < 12; j++) ffma2(acc[j], wv, xx[j + k]);
            }
        }
        __syncthreads();

        if (cis > 0) {
            float* pr = &red[(size_t)(cis - 1) * 2304];
#pragma unroll
            for (int j = 0; j < 12; j++) {
                int l = lg * 12 + j;
                float a, b2; unpack2(acc[j], a, b2);
                pr[(bsel * 32 + 2 * cp + 0) * W_L + l] = a;
                pr[(bsel * 32 + 2 * cp + 1) * W_L + l] = b2;
            }
        }
        __syncthreads();

        if (cis == 0) {
            float fin[24];
#pragma unroll
            for (int j = 0; j < 12; j++) {
                int l = lg * 12 + j;
                int f0 = (bsel * 32 + 2 * cp + 0) * W_L + l;
                int f1 = (bsel * 32 + 2 * cp + 1) * W_L + l;
                float a, b2; unpack2(acc[j], a, b2);
                a  += red[f0] + red[2304 + f0] + red[4608 + f0];
                b2 += red[f1] + red[2304 + f1] + red[4608 + f1];
                fin[j]      = ((const float*)og)[j]      + fmaxf(a, 0.f);
                fin[12 + j] = ((const float*)og)[12 + j] + fmaxf(b2, 0.f);
            }
#pragma unroll
            for (int q = 0; q < 2; q++) {
                float4* dst = (float4*)
                    &buf[(((size_t)(b0 + bsel) * CC + co_base + 2 * cp + q) * W_S + s_dst)
                         * W_L + lg * 12];
                float4* nst = (float4*)
                    &newcol[(bsel * 32 + 2 * cp + q) * W_L + lg * 12];
#pragma unroll
                for (int t = 0; t < 3; t++) {
                    float4 v = ((const float4*)fin)[q * 3 + t];
                    dst[t] = v;
                    nst[t] = v;
                }
            }
        }
        __syncthreads();

        cluster_sync();

        for (int idx = tid; idx < 2 * 32 * (W_L / 2); idx += W_NT) {
            int bs = idx / (32 * 18);
            int r  = idx % (32 * 18);
            int co = r / 18, q = r % 18;
            u64 v = ((const u64*)&newcol[(bs * 32 + co) * W_L])[q];
            unsigned loff = state_u32 +
                (unsigned)(((bs * CC + co_base + co) * W_ROW + 4) * 4 + q * 8);
#pragma unroll
            for (unsigned rk = 0; rk < 4; rk++)
                st_cluster64(mapa_u32(loff, rk), v);
        }

        cluster_sync();
    }
}

// [co][ci][k] -> [ci*9+k][co] for all 4 sets
__global__ void prep_w4(const float* __restrict__ w0, const float* __restrict__ w1,
                        const float* __restrict__ w2, const float* __restrict__ w3,
                        float* __restrict__ wt)
{
    int idx = blockIdx.x * 256 + threadIdx.x;
    if (idx < CC * CC * KK) {
        int co = idx / (CC * KK);
        int rem = idx % (CC * KK);
        int ci = rem / KK, k = rem % KK;
        size_t o = ((size_t)ci * KK + k) * CC + co;
        const size_t SZ = (size_t)CC * CC * KK;
        wt[o] = w0[idx];
        wt[SZ + o] = w1[idx];
        wt[2 * SZ + o] = w2[idx];
        wt[3 * SZ + o] = w3[idx];
    }
}

// Slice-resident transpose: one CTA per bc slice [R][Cc] -> [Cc][R].
// Padded SMEM (stride+1) => conflict-free; both global sides coalesced.
template <int R, int Cc>
__global__ __launch_bounds__(256, 8) void transpose_slice(
    const float* __restrict__ in, float* __restrict__ out)
{
    __shared__ float t[R * (Cc + 1)];
    const int bc = blockIdx.x;
    const float* ip = in + (size_t)bc * R * Cc;
    float* op = out + (size_t)bc * R * Cc;
    const int tid = threadIdx.x;

    for (int i = tid; i < R * Cc; i += 256) {
        int r = i / Cc, c = i % Cc;
        t[r * (Cc + 1) + c] = ip[i];
    }
    __syncthreads();
    for (int i = tid; i < R * Cc; i += 256) {
        int c = i / R, r = i % R;
        op[i] = t[r * (Cc + 1) + c];
    }
}

extern "C" void kernel_launch(void* const* d_in, const int* in_sizes, int n_in,
                              void* d_out, int out_size)
{
    const float* x   = (const float*)d_in[0];
    const float* w_d = (const float*)d_in[1];
    const float* b_d = (const float*)d_in[2];
    const float* w_u = (const float*)d_in[3];
    const float* b_u = (const float*)d_in[4];
    const float* w_r = (const float*)d_in[5];
    const float* b_r = (const float*)d_in[6];
    const float* w_l = (const float*)d_in[7];
    const float* b_l = (const float*)d_in[8];
    float* out = (float*)d_out;

    float* T = nullptr;
    cudaGetSymbolAddress((void**)&T, g_T);
    float* Wt = nullptr;
    cudaGetSymbolAddress((void**)&Wt, g_Wt);
    const size_t SZ = (size_t)CC * CC * KK;
    float* wt_d = Wt;
    float* wt_u = Wt + SZ;
    float* wt_r = Wt + 2 * SZ;
    float* wt_l = Wt + 3 * SZ;

    dummy_kernel<<<1, 32>>>();
    dummy_kernel<<<1, 32>>>();

    const int WG = (CC * CC * KK + 255) / 256;
    prep_w4<<<WG, 256>>>(w_d, w_u, w_r, w_l, Wt);

    const size_t nbytes = (size_t)BB * CC * HH * WW * sizeof(float);
    cudaMemcpyAsync(out, x, nbytes, cudaMemcpyDeviceToDevice, 0);

    // H passes: 320 thr, smem 202752 B.
    {
        constexpr int SMEM_H = (CC * KK * 32 + 2 * 2 * 32 * 108) * 4;
        cudaFuncSetAttribute(pass_kernel<WW, HH, 8, 10, 10, 2>,
                             cudaFuncAttributeMaxDynamicSharedMemorySize, SMEM_H);
        dim3 g(4, 32);
        pass_kernel<WW, HH, 8, 10, 10, 2><<<g, 320, SMEM_H>>>(out, wt_d, b_d, 1, HH - 1, +1);
        pass_kernel<WW, HH, 8, 10, 10, 2><<<g, 320, SMEM_H>>>(out, wt_u, b_u, HH - 2, HH - 2, -1);
    }

    // Transpose [B,C,H,W] -> [B,C,W,H]: one CTA per 36x100 slice.
    transpose_slice<HH, WW><<<BB * CC, 256>>>(out, T);

    // W passes: cluster-4 DSMEM kernel, 384 thr, smem 229376 B.
    {
        constexpr int SMEM_W = (CC * KK * 32 + 2 * CC * W_ROW + 3 * 2304 + 2304) * 4;
        cudaFuncSetAttribute(wpass_kernel,
                             cudaFuncAttributeMaxDynamicSharedMemorySize, SMEM_W);
        dim3 g(4, 32);
        wpass_kernel<<<g, W_NT, SMEM_W>>>(T, wt_r, b_r, 1, WW - 1, +1);
        wpass_kernel<<<g, W_NT, SMEM_W>>>(T, wt_l, b_l, WW - 2, WW - 2, -1);
    }

    // Transpose back [B,C,W,H] -> [B,C,H,W].
    transpose_slice<WW, HH><<<BB * CC, 256>>>(T, out);
}